// round 15
// baseline (speedup 1.0000x reference)
#include <cuda_runtime.h>
#include <cuda_bf16.h>
#include <math_constants.h>

// CRF neg-log-likelihood, GB300 sm_103a.
// TWO batch rows per CTA (32 CTAs x 64 threads). Per superstep, BOTH rows'
// GEMVs (loads+FMAs) execute before EITHER row's store -> the two independent
// chains interleave at the SASS level and hide each other's LDS/FMA latency;
// one nw=2 __syncthreads covers both exchanges. Per-row math identical to the
// verified R14 loop: bf16 partition ping-pong, 25-word buffer, 25 HFMA2 into
// 8 accs, all-bf16 epilogue, splatted-ef smem tables, rescale by p[0] every
// 4 steps, mask fast path.

namespace {
constexpr int NTAG   = 50;
constexpr int TSTART = NTAG - 2;   // 48
constexpr int TSTOP  = NTAG - 1;   // 49
constexpr int BATCH  = 64;
constexpr int SEQ    = 512;
constexpr int NTHR   = 64;
constexpr int R      = 2;
constexpr int NCTA   = BATCH / R;  // 32
constexpr int NPW    = 25;         // partition pair-words
constexpr int EFW    = SEQ * NTAG;                 // words per ef table
constexpr int MSKW   = SEQ + 1;
constexpr int SMEM_BYTES = (2 * EFW + 2 * MSKW) * 4;   // ~208.9 KB
}

__device__ float    g_partial[BATCH];
__device__ unsigned g_ticket = 0;

__device__ __forceinline__ float warpSumF(float v) {
#pragma unroll
    for (int o = 16; o > 0; o >>= 1) v += __shfl_xor_sync(0xffffffffu, v, o);
    return v;
}
__device__ __forceinline__ int warpSumI(int v) {
#pragma unroll
    for (int o = 16; o > 0; o >>= 1) v += __shfl_xor_sync(0xffffffffu, v, o);
    return v;
}
__device__ __forceinline__ __nv_bfloat162 asbf2(float f) {
    return *reinterpret_cast<__nv_bfloat162*>(&f);
}
__device__ __forceinline__ __nv_bfloat162 u2b(unsigned u) {
    return *reinterpret_cast<__nv_bfloat162*>(&u);
}
__device__ __forceinline__ unsigned b2u(__nv_bfloat162 b) {
    return *reinterpret_cast<unsigned*>(&b);
}
__device__ __forceinline__ unsigned swap16(unsigned a) {
    unsigned r; asm("prmt.b32 %0, %1, 0, 0x1032;" : "=r"(r) : "r"(a)); return r;
}

// GEMV core (verified R14): 6 LDS.128 + 1 LDS.32, 25 HFMA2, depth-4, 7 HADD2.
__device__ __forceinline__ __nv_bfloat162 gemv25(
    const unsigned* __restrict__ src,
    const __nv_bfloat162 (&et2)[NPW],
    float& p0f)
{
    const float4* sp4 = (const float4*)src;
    float4 v0 = sp4[0];
    float4 v1 = sp4[1];
    float4 v2 = sp4[2];
    float4 v3 = sp4[3];
    float4 v4 = sp4[4];
    float4 v5 = sp4[5];
    unsigned w24 = src[24];

    p0f = __uint_as_float(__float_as_uint(v0.x) << 16);

    __nv_bfloat162 z = __floats2bfloat162_rn(0.f, 0.f);
    __nv_bfloat162 a0 = z, a1 = z, a2 = z, a3 = z;
    __nv_bfloat162 a4 = z, a5 = z, a6 = z, a7 = z;

    a0 = __hfma2(asbf2(v0.x), et2[0],  a0);
    a1 = __hfma2(asbf2(v0.y), et2[1],  a1);
    a2 = __hfma2(asbf2(v0.z), et2[2],  a2);
    a3 = __hfma2(asbf2(v0.w), et2[3],  a3);
    a4 = __hfma2(asbf2(v1.x), et2[4],  a4);
    a5 = __hfma2(asbf2(v1.y), et2[5],  a5);
    a6 = __hfma2(asbf2(v1.z), et2[6],  a6);
    a7 = __hfma2(asbf2(v1.w), et2[7],  a7);
    a0 = __hfma2(asbf2(v2.x), et2[8],  a0);
    a1 = __hfma2(asbf2(v2.y), et2[9],  a1);
    a2 = __hfma2(asbf2(v2.z), et2[10], a2);
    a3 = __hfma2(asbf2(v2.w), et2[11], a3);
    a4 = __hfma2(asbf2(v3.x), et2[12], a4);
    a5 = __hfma2(asbf2(v3.y), et2[13], a5);
    a6 = __hfma2(asbf2(v3.z), et2[14], a6);
    a7 = __hfma2(asbf2(v3.w), et2[15], a7);
    a0 = __hfma2(asbf2(v4.x), et2[16], a0);
    a1 = __hfma2(asbf2(v4.y), et2[17], a1);
    a2 = __hfma2(asbf2(v4.z), et2[18], a2);
    a3 = __hfma2(asbf2(v4.w), et2[19], a3);
    a4 = __hfma2(asbf2(v5.x), et2[20], a4);
    a5 = __hfma2(asbf2(v5.y), et2[21], a5);
    a6 = __hfma2(asbf2(v5.z), et2[22], a6);
    a7 = __hfma2(asbf2(v5.w), et2[23], a7);
    a0 = __hfma2(u2b(w24),    et2[24], a0);

    a0 = __hadd2(a0, a4);
    a1 = __hadd2(a1, a5);
    a2 = __hadd2(a2, a6);
    a3 = __hadd2(a3, a7);
    a0 = __hadd2(a0, a1);
    a2 = __hadd2(a2, a3);
    return __hadd2(a0, a2);
}

// FAST superstep (masks==1 for both rows): both GEMVs, then both stores.
template <bool RESCALE>
__device__ __forceinline__ void step2_fast(
    int t, int j, int jf, bool act,
    const unsigned* __restrict__ src0, unsigned* __restrict__ dst0,
    const unsigned* __restrict__ src1, unsigned* __restrict__ dst1,
    const __nv_bfloat162 (&et2)[NPW],
    unsigned& efw0, unsigned& efw1,
    float& off0, float& off1,
    const unsigned* __restrict__ s_ef0,
    const unsigned* __restrict__ s_ef1)
{
    float p00, p01;
    __nv_bfloat162 s20 = gemv25(src0, et2, p00);   // all loads precede
    __nv_bfloat162 s21 = gemv25(src1, et2, p01);   // any store below

    float rp0 = 1.f, rp1 = 1.f;
    if (RESCALE) { rp0 = __frcp_rn(p00); rp1 = __frcp_rn(p01); }

    s20 = __hadd2(s20, u2b(swap16(b2u(s20))));
    s21 = __hadd2(s21, u2b(swap16(b2u(s21))));
    __nv_bfloat162 q20 = __hmul2(s20, u2b(efw0));
    __nv_bfloat162 q21 = __hmul2(s21, u2b(efw1));
    if (RESCALE) {
        q20 = __hmul2(q20, __float2bfloat162_rn(rp0));
        q21 = __hmul2(q21, __float2bfloat162_rn(rp1));
    }

    if (act) {
        ((__nv_bfloat16*)dst0)[j] = __low2bfloat16(q20);
        ((__nv_bfloat16*)dst1)[j] = __low2bfloat16(q21);
    }

    efw0 = s_ef0[(t + 1) * NTAG + jf];
    efw1 = s_ef1[(t + 1) * NTAG + jf];
    if (RESCALE) { off0 += __logf(p00); off1 += __logf(p01); }

    __syncthreads();
}

// GENERAL superstep: honors per-row masks.
template <bool RESCALE>
__device__ __forceinline__ void step2_gen(
    int t, int j, int jf, bool act,
    const unsigned* __restrict__ src0, unsigned* __restrict__ dst0,
    const unsigned* __restrict__ src1, unsigned* __restrict__ dst1,
    const __nv_bfloat162 (&et2)[NPW],
    unsigned& efw0, unsigned& efw1,
    unsigned& pj0, unsigned& pj1,
    float& off0, float& off1, int& m0, int& m1,
    const unsigned* __restrict__ s_ef0,
    const unsigned* __restrict__ s_ef1,
    const int* __restrict__ s_m0,
    const int* __restrict__ s_m1)
{
    float p00, p01;
    __nv_bfloat162 s20 = gemv25(src0, et2, p00);
    __nv_bfloat162 s21 = gemv25(src1, et2, p01);

    float rp0 = 1.f, rp1 = 1.f;
    if (RESCALE) { rp0 = __frcp_rn(p00); rp1 = __frcp_rn(p01); }

    s20 = __hadd2(s20, u2b(swap16(b2u(s20))));
    s21 = __hadd2(s21, u2b(swap16(b2u(s21))));
    unsigned q0 = b2u(__hmul2(s20, u2b(efw0)));
    unsigned q1 = b2u(__hmul2(s21, u2b(efw1)));
    q0 = m0 ? q0 : pj0;
    q1 = m1 ? q1 : pj1;
    if (RESCALE) {
        q0 = b2u(__hmul2(u2b(q0), __float2bfloat162_rn(rp0)));
        q1 = b2u(__hmul2(u2b(q1), __float2bfloat162_rn(rp1)));
    }
    pj0 = q0; pj1 = q1;

    if (act) {
        ((__nv_bfloat16*)dst0)[j] = __low2bfloat16(u2b(q0));
        ((__nv_bfloat16*)dst1)[j] = __low2bfloat16(u2b(q1));
    }

    efw0 = s_ef0[(t + 1) * NTAG + jf];
    efw1 = s_ef1[(t + 1) * NTAG + jf];
    m0 = s_m0[t + 1];
    m1 = s_m1[t + 1];
    if (RESCALE) { off0 += __logf(p00); off1 += __logf(p01); }

    __syncthreads();
}

__global__ void __launch_bounds__(NTHR, 1)
crf_kernel(const float* __restrict__ feats,
           const int*   __restrict__ mask,
           const int*   __restrict__ tags,
           const float* __restrict__ trans,
           float*       __restrict__ out)
{
    const int g    = blockIdx.x;          // rows 2g, 2g+1
    const int j    = threadIdx.x;
    const int jf   = min(j, NTAG - 1);
    const int lane = j & 31;
    const int wid  = j >> 5;
    const bool act = (j < NTAG);

    extern __shared__ unsigned dyn[];
    unsigned* s_ef0 = dyn;                 // [SEQ][NTAG] splatted ef, row 0
    unsigned* s_ef1 = dyn + EFW;           // row 1
    int* s_m0 = (int*)(dyn + 2 * EFW);     // [SEQ+1]
    int* s_m1 = s_m0 + MSKW;

    __shared__ __align__(16) unsigned spA0[NPW + 3];
    __shared__ __align__(16) unsigned spB0[NPW + 3];
    __shared__ __align__(16) unsigned spA1[NPW + 3];
    __shared__ __align__(16) unsigned spB1[NPW + 3];
    __shared__ float s_fwd[R];
    __shared__ float s_gold[R];
    __shared__ int   s_ones[2];
    __shared__ bool  s_last;
    __shared__ float s_red2[2];

    const float* fb0 = feats + (long long)(2 * g)     * SEQ * NTAG;
    const float* fb1 = feats + (long long)(2 * g + 1) * SEQ * NTAG;
    const int*   mb0 = mask + (2 * g) * SEQ;
    const int*   mb1 = mask + (2 * g + 1) * SEQ;
    const int*   tb0 = tags + (2 * g) * SEQ;
    const int*   tb1 = tags + (2 * g + 1) * SEQ;

    // ---- prologue: masks + all-ones count + splatted exp(feats) x2 ----
    {
        int cnt = 0;
        for (int t = j; t < SEQ; t += NTHR) {
            int v0 = mb0[t], v1 = mb1[t];
            s_m0[t] = v0; s_m1[t] = v1;
            cnt += v0 + v1;
        }
        cnt = warpSumI(cnt);
        if (lane == 0) s_ones[wid] = cnt;
        if (j == 0) { s_m0[SEQ] = 0; s_m1[SEQ] = 0; }
    }
    {
        const float4* f40 = (const float4*)fb0;
        const float4* f41 = (const float4*)fb1;
#pragma unroll 2
        for (int idx = j; idx < SEQ * NTAG / 4; idx += NTHR) {
            float4 v0 = f40[idx];
            float4 v1 = f41[idx];
            uint4 e0, e1;
            e0.x = b2u(__float2bfloat162_rn(__expf(v0.x)));
            e0.y = b2u(__float2bfloat162_rn(__expf(v0.y)));
            e0.z = b2u(__float2bfloat162_rn(__expf(v0.z)));
            e0.w = b2u(__float2bfloat162_rn(__expf(v0.w)));
            e1.x = b2u(__float2bfloat162_rn(__expf(v1.x)));
            e1.y = b2u(__float2bfloat162_rn(__expf(v1.y)));
            e1.z = b2u(__float2bfloat162_rn(__expf(v1.z)));
            e1.w = b2u(__float2bfloat162_rn(__expf(v1.w)));
            ((uint4*)s_ef0)[idx] = e0;
            ((uint4*)s_ef1)[idx] = e1;
        }
    }

    // exp(transitions) column j (shared by both rows)
    __nv_bfloat162 et2[NPW];
    if (act) {
#pragma unroll
        for (int k = 0; k < NPW; k++) {
            float e0 = __expf(trans[(2 * k)     * NTAG + j]);
            float e1 = __expf(trans[(2 * k + 1) * NTAG + j]);
            et2[k] = __floats2bfloat162_rn(e0, e1);
        }
    } else {
#pragma unroll
        for (int k = 0; k < NPW; k++) et2[k] = __floats2bfloat162_rn(0.f, 0.f);
    }

    // t = 0 init per row
    const float o00 = fb0[0] + trans[TSTART * NTAG + 0];
    const float o01 = fb1[0] + trans[TSTART * NTAG + 0];
    float off0 = o00, off1 = o01;
    float p0a = act ? __expf(fb0[j] + trans[TSTART * NTAG + j] - o00) : 0.f;
    float p0b = act ? __expf(fb1[j] + trans[TSTART * NTAG + j] - o01) : 0.f;
    unsigned pj0 = b2u(__float2bfloat162_rn(p0a));
    unsigned pj1 = b2u(__float2bfloat162_rn(p0b));
    if (act) {
        ((__nv_bfloat16*)spA0)[j] = __low2bfloat16(u2b(pj0));
        ((__nv_bfloat16*)spA1)[j] = __low2bfloat16(u2b(pj1));
    }
    __syncthreads();

    const bool allOnes = (s_ones[0] + s_ones[1]) == 2 * SEQ;
    unsigned efw0 = s_ef0[1 * NTAG + jf];
    unsigned efw1 = s_ef1[1 * NTAG + jf];

    if (allOnes) {
        for (int t = 1; t + 3 < SEQ; t += 4) {
            step2_fast<false>(t,     j, jf, act, spA0, spB0, spA1, spB1, et2, efw0, efw1, off0, off1, s_ef0, s_ef1);
            step2_fast<false>(t + 1, j, jf, act, spB0, spA0, spB1, spA1, et2, efw0, efw1, off0, off1, s_ef0, s_ef1);
            step2_fast<false>(t + 2, j, jf, act, spA0, spB0, spA1, spB1, et2, efw0, efw1, off0, off1, s_ef0, s_ef1);
            step2_fast<true >(t + 3, j, jf, act, spB0, spA0, spB1, spA1, et2, efw0, efw1, off0, off1, s_ef0, s_ef1);
        }
        step2_fast<false>(SEQ - 3, j, jf, act, spA0, spB0, spA1, spB1, et2, efw0, efw1, off0, off1, s_ef0, s_ef1);
        step2_fast<false>(SEQ - 2, j, jf, act, spB0, spA0, spB1, spA1, et2, efw0, efw1, off0, off1, s_ef0, s_ef1);
        {   // final step inline, both rows
            float p00, p01;
            __nv_bfloat162 s20 = gemv25(spA0, et2, p00);
            __nv_bfloat162 s21 = gemv25(spA1, et2, p01);
            s20 = __hadd2(s20, u2b(swap16(b2u(s20))));
            s21 = __hadd2(s21, u2b(swap16(b2u(s21))));
            __nv_bfloat162 q20 = __hmul2(s20, u2b(efw0));
            __nv_bfloat162 q21 = __hmul2(s21, u2b(efw1));
            if (act) {
                ((__nv_bfloat16*)spB0)[j] = __low2bfloat16(q20);
                ((__nv_bfloat16*)spB1)[j] = __low2bfloat16(q21);
            }
            __syncthreads();
        }
    } else {
        int m0 = s_m0[1], m1 = s_m1[1];
        for (int t = 1; t + 3 < SEQ; t += 4) {
            step2_gen<false>(t,     j, jf, act, spA0, spB0, spA1, spB1, et2, efw0, efw1, pj0, pj1, off0, off1, m0, m1, s_ef0, s_ef1, s_m0, s_m1);
            step2_gen<false>(t + 1, j, jf, act, spB0, spA0, spB1, spA1, et2, efw0, efw1, pj0, pj1, off0, off1, m0, m1, s_ef0, s_ef1, s_m0, s_m1);
            step2_gen<false>(t + 2, j, jf, act, spA0, spB0, spA1, spB1, et2, efw0, efw1, pj0, pj1, off0, off1, m0, m1, s_ef0, s_ef1, s_m0, s_m1);
            step2_gen<true >(t + 3, j, jf, act, spB0, spA0, spB1, spA1, et2, efw0, efw1, pj0, pj1, off0, off1, m0, m1, s_ef0, s_ef1, s_m0, s_m1);
        }
        step2_gen<false>(SEQ - 3, j, jf, act, spA0, spB0, spA1, spB1, et2, efw0, efw1, pj0, pj1, off0, off1, m0, m1, s_ef0, s_ef1, s_m0, s_m1);
        step2_gen<false>(SEQ - 2, j, jf, act, spB0, spA0, spB1, spA1, et2, efw0, efw1, pj0, pj1, off0, off1, m0, m1, s_ef0, s_ef1, s_m0, s_m1);
        {
            float p00, p01;
            __nv_bfloat162 s20 = gemv25(spA0, et2, p00);
            __nv_bfloat162 s21 = gemv25(spA1, et2, p01);
            s20 = __hadd2(s20, u2b(swap16(b2u(s20))));
            s21 = __hadd2(s21, u2b(swap16(b2u(s21))));
            unsigned q0 = b2u(__hmul2(s20, u2b(efw0)));
            unsigned q1 = b2u(__hmul2(s21, u2b(efw1)));
            q0 = m0 ? q0 : pj0;
            q1 = m1 ? q1 : pj1;
            if (act) {
                ((__nv_bfloat16*)spB0)[j] = __low2bfloat16(u2b(q0));
                ((__nv_bfloat16*)spB1)[j] = __low2bfloat16(u2b(q1));
            }
            __syncthreads();
        }
    }

    // terminal for both rows (thread TSTOP owns column STOP)
    if (j == TSTOP) {
        float pp;
        __nv_bfloat162 s20 = gemv25(spB0, et2, pp);
        __nv_bfloat162 s21 = gemv25(spB1, et2, pp);
        float2 f0 = __bfloat1622float2(s20);
        float2 f1 = __bfloat1622float2(s21);
        s_fwd[0] = __logf(f0.x + f0.y) + off0;
        s_fwd[1] = __logf(f1.x + f1.y) + off1;
    }

    // ---- gold scores: warp w handles row w ----
    {
        const float* fb = wid ? fb1 : fb0;
        const int*   tb = wid ? tb1 : tb0;
        const int*   sm = wid ? s_m1 : s_m0;
        float acc = 0.f;
        int   len = 0;
#pragma unroll 4
        for (int t = lane; t < SEQ; t += 32) {
            int tag  = tb[t];
            int prev = (t == 0) ? TSTART : tb[t - 1];
            int mm   = sm[t];
            if (mm) acc += fb[t * NTAG + tag] + trans[prev * NTAG + tag];
            len += mm;
        }
        acc = warpSumF(acc);
        len = warpSumI(len);
        if (lane == 0) {
            int endid = tb[len - 1];
            s_gold[wid] = acc + trans[endid * NTAG + TSTOP];
        }
    }
    __syncthreads();

    if (j < R) {
        g_partial[2 * g + j] = s_fwd[j] - s_gold[j];
        __threadfence();
    }
    __syncthreads();
    if (j == 0) {
        unsigned tk = atomicAdd(&g_ticket, 1u);
        s_last = (tk == NCTA - 1);
    }
    __syncthreads();

    if (s_last) {
        float v = ((volatile float*)g_partial)[j];
        v = warpSumF(v);
        if (lane == 0) s_red2[wid] = v;
        __syncthreads();
        if (j == 0) {
            out[0] = s_red2[0] + s_red2[1];
            g_ticket = 0;
        }
    }
}

extern "C" void kernel_launch(void* const* d_in, const int* in_sizes, int n_in,
                              void* d_out, int out_size)
{
    const float* feats = (const float*)d_in[0];
    const int*   mask  = (const int*)d_in[1];
    const int*   tags  = (const int*)d_in[2];
    const float* trans = (const float*)d_in[3];
    float* out = (float*)d_out;

    cudaFuncSetAttribute(crf_kernel,
                         cudaFuncAttributeMaxDynamicSharedMemorySize, SMEM_BYTES);
    crf_kernel<<<NCTA, NTHR, SMEM_BYTES>>>(feats, mask, tags, trans, out);
}

// round 16
// speedup vs baseline: 1.5882x; 1.5882x over previous
#include <cuda_runtime.h>
#include <cuda_bf16.h>
#include <math_constants.h>

// CRF neg-log-likelihood, GB300 sm_103a.
// 64 CTAs x 64 threads (2 warps). Minimal-chain loop (R14 lineage):
// - linear-space forward recursion, bf16 partition smem ping-pong
// - partition buffer exactly 25 u32: LDS.32 (word 24) issued FIRST, then
//   6 LDS.128; 25 HFMA2 into 8 accs, late-load pair joins the tree last
// - exp(feats) precomputed to dynamic smem as SPLATTED bf162 words
// - mask fast path (no mask LDS / SEL / carry in the loop)
// - all-bf16 epilogue: swap-add + HMUL2 + STS.U16
// - rescale by p_prev[0] every 4 steps; loop unrolled 8 steps/iteration

namespace {
constexpr int NTAG   = 50;
constexpr int TSTART = NTAG - 2;   // 48
constexpr int TSTOP  = NTAG - 1;   // 49
constexpr int BATCH  = 64;
constexpr int SEQ    = 512;
constexpr int NTHR   = 64;
constexpr int NPW    = 25;         // partition pair-words (exact)
constexpr int SMEM_EF_WORDS = SEQ * NTAG;       // splatted bf162 exp(feats)
constexpr int SMEM_BYTES    = SMEM_EF_WORDS * 4;
}

__device__ float    g_partial[BATCH];
__device__ unsigned g_ticket = 0;

__device__ __forceinline__ float warpSumF(float v) {
#pragma unroll
    for (int o = 16; o > 0; o >>= 1) v += __shfl_xor_sync(0xffffffffu, v, o);
    return v;
}
__device__ __forceinline__ int warpSumI(int v) {
#pragma unroll
    for (int o = 16; o > 0; o >>= 1) v += __shfl_xor_sync(0xffffffffu, v, o);
    return v;
}
__device__ __forceinline__ __nv_bfloat162 asbf2(float f) {
    return *reinterpret_cast<__nv_bfloat162*>(&f);
}
__device__ __forceinline__ __nv_bfloat162 u2b(unsigned u) {
    return *reinterpret_cast<__nv_bfloat162*>(&u);
}
__device__ __forceinline__ unsigned b2u(__nv_bfloat162 b) {
    return *reinterpret_cast<unsigned*>(&b);
}
__device__ __forceinline__ unsigned swap16(unsigned a) {
    unsigned r; asm("prmt.b32 %0, %1, 0, 0x1032;" : "=r"(r) : "r"(a)); return r;
}

// GEMV core: LDS.32 first, 6 LDS.128; 25 HFMA2 into 8 accs.
// a7 takes {k24(early), k7, k15, k23(last load)} so the late load feeds one
// FMA then the tree; the late pair (a3+a7) merges last.
__device__ __forceinline__ __nv_bfloat162 gemv25(
    const unsigned* __restrict__ src,
    const __nv_bfloat162 (&et2)[NPW],
    float& p0f)
{
    unsigned w24 = src[24];                  // issued first
    const float4* sp4 = (const float4*)src;
    float4 v0 = sp4[0];
    float4 v1 = sp4[1];
    float4 v2 = sp4[2];
    float4 v3 = sp4[3];
    float4 v4 = sp4[4];
    float4 v5 = sp4[5];

    p0f = __uint_as_float(__float_as_uint(v0.x) << 16);

    __nv_bfloat162 z = __floats2bfloat162_rn(0.f, 0.f);
    __nv_bfloat162 a0 = z, a1 = z, a2 = z, a3 = z;
    __nv_bfloat162 a4 = z, a5 = z, a6 = z, a7 = z;

    a7 = __hfma2(u2b(w24),    et2[24], a7);  // earliest operand
    a0 = __hfma2(asbf2(v0.x), et2[0],  a0);
    a1 = __hfma2(asbf2(v0.y), et2[1],  a1);
    a2 = __hfma2(asbf2(v0.z), et2[2],  a2);
    a3 = __hfma2(asbf2(v0.w), et2[3],  a3);
    a4 = __hfma2(asbf2(v1.x), et2[4],  a4);
    a5 = __hfma2(asbf2(v1.y), et2[5],  a5);
    a6 = __hfma2(asbf2(v1.z), et2[6],  a6);
    a7 = __hfma2(asbf2(v1.w), et2[7],  a7);
    a0 = __hfma2(asbf2(v2.x), et2[8],  a0);
    a1 = __hfma2(asbf2(v2.y), et2[9],  a1);
    a2 = __hfma2(asbf2(v2.z), et2[10], a2);
    a3 = __hfma2(asbf2(v2.w), et2[11], a3);
    a4 = __hfma2(asbf2(v3.x), et2[12], a4);
    a5 = __hfma2(asbf2(v3.y), et2[13], a5);
    a6 = __hfma2(asbf2(v3.z), et2[14], a6);
    a7 = __hfma2(asbf2(v3.w), et2[15], a7);
    a0 = __hfma2(asbf2(v4.x), et2[16], a0);
    a1 = __hfma2(asbf2(v4.y), et2[17], a1);
    a2 = __hfma2(asbf2(v4.z), et2[18], a2);
    a3 = __hfma2(asbf2(v4.w), et2[19], a3);
    a4 = __hfma2(asbf2(v5.x), et2[20], a4);
    a5 = __hfma2(asbf2(v5.y), et2[21], a5);
    a6 = __hfma2(asbf2(v5.z), et2[22], a6);
    a7 = __hfma2(asbf2(v5.w), et2[23], a7);  // last load's only FMA

    // tree: late (a3..a7-side) merges last
    __nv_bfloat162 c0 = __hadd2(__hadd2(a0, a4), __hadd2(a1, a5));
    __nv_bfloat162 c1 = __hadd2(__hadd2(a2, a6), __hadd2(a3, a7));
    return __hadd2(c0, c1);
}

// FAST step (mask==1): all-bf16 epilogue, no SEL/carry.
template <bool RESCALE>
__device__ __forceinline__ void step_fast(
    int t, int j, int jf, bool act,
    const unsigned* __restrict__ src,
    unsigned*       __restrict__ dst,
    const __nv_bfloat162 (&et2)[NPW],
    unsigned& efw, float& offset,
    const unsigned* __restrict__ s_ef)
{
    float p0f;
    __nv_bfloat162 s2 = gemv25(src, et2, p0f);
    float rp0 = 1.f;
    if (RESCALE) rp0 = __frcp_rn(p0f);

    s2 = __hadd2(s2, u2b(swap16(b2u(s2))));      // total in both halves
    __nv_bfloat162 q2 = __hmul2(s2, u2b(efw));   // * splatted ef
    if (RESCALE) q2 = __hmul2(q2, __float2bfloat162_rn(rp0));

    if (act) ((__nv_bfloat16*)dst)[j] = __low2bfloat16(q2);   // STS.U16

    efw = s_ef[(t + 1) * NTAG + jf];             // off-path prefetch
    if (RESCALE) offset += __logf(p0f);

    __syncthreads();
}

// GENERAL step: honors mask (carry previous).
template <bool RESCALE>
__device__ __forceinline__ void step_gen(
    int t, int j, int jf, bool act,
    const unsigned* __restrict__ src,
    unsigned*       __restrict__ dst,
    const __nv_bfloat162 (&et2)[NPW],
    unsigned& efw, unsigned& pju, float& offset, int& m,
    const unsigned* __restrict__ s_ef,
    const int*      __restrict__ s_mask)
{
    float p0f;
    __nv_bfloat162 s2 = gemv25(src, et2, p0f);
    float rp0 = 1.f;
    if (RESCALE) rp0 = __frcp_rn(p0f);

    s2 = __hadd2(s2, u2b(swap16(b2u(s2))));
    unsigned q2u = b2u(__hmul2(s2, u2b(efw)));
    q2u = m ? q2u : pju;
    if (RESCALE) q2u = b2u(__hmul2(u2b(q2u), __float2bfloat162_rn(rp0)));
    pju = q2u;

    if (act) ((__nv_bfloat16*)dst)[j] = __low2bfloat16(u2b(q2u));

    efw = s_ef[(t + 1) * NTAG + jf];
    m   = s_mask[t + 1];
    if (RESCALE) offset += __logf(p0f);

    __syncthreads();
}

__global__ void __launch_bounds__(NTHR, 1)
crf_kernel(const float* __restrict__ feats,
           const int*   __restrict__ mask,
           const int*   __restrict__ tags,
           const float* __restrict__ trans,
           float*       __restrict__ out)
{
    const int b    = blockIdx.x;
    const int j    = threadIdx.x;
    const int jf   = min(j, NTAG - 1);
    const int lane = j & 31;
    const int wid  = j >> 5;
    const bool act = (j < NTAG);

    extern __shared__ unsigned s_ef[];       // [SEQ][NTAG] splatted bf162 ef

    __shared__ __align__(16) unsigned spA[NPW + 3];
    __shared__ __align__(16) unsigned spB[NPW + 3];
    __shared__ float s_fwd;
    __shared__ float s_acc[2];
    __shared__ int   s_len[2];
    __shared__ int   s_mask[SEQ + 1];
    __shared__ int   s_ones[2];
    __shared__ bool  s_last;
    __shared__ float s_red2[2];

    const float* fb = feats + (long long)b * SEQ * NTAG;
    const int*   mb = mask  + b * SEQ;
    const int*   tb = tags  + b * SEQ;

    // ---- prologue: mask + all-ones count + splatted exp(feats) ----
    {
        int cnt = 0;
        for (int t = j; t < SEQ; t += NTHR) { int v = mb[t]; s_mask[t] = v; cnt += v; }
        cnt = warpSumI(cnt);
        if (lane == 0) s_ones[wid] = cnt;
        if (j == 0) s_mask[SEQ] = 0;
    }
    {
        const float4* f4 = (const float4*)fb;    // 6400 float4
#pragma unroll 4
        for (int idx = j; idx < SEQ * NTAG / 4; idx += NTHR) {
            float4 v = f4[idx];
            uint4 e;
            e.x = b2u(__float2bfloat162_rn(__expf(v.x)));
            e.y = b2u(__float2bfloat162_rn(__expf(v.y)));
            e.z = b2u(__float2bfloat162_rn(__expf(v.z)));
            e.w = b2u(__float2bfloat162_rn(__expf(v.w)));
            ((uint4*)s_ef)[idx] = e;
        }
    }

    // exp(transitions) column j: et2[k] = (e^T[2k][j], e^T[2k+1][j])
    __nv_bfloat162 et2[NPW];
    if (act) {
#pragma unroll
        for (int k = 0; k < NPW; k++) {
            float e0 = __expf(trans[(2 * k)     * NTAG + j]);
            float e1 = __expf(trans[(2 * k + 1) * NTAG + j]);
            et2[k] = __floats2bfloat162_rn(e0, e1);
        }
    } else {
#pragma unroll
        for (int k = 0; k < NPW; k++) et2[k] = __floats2bfloat162_rn(0.f, 0.f);
    }

    // t = 0: normalize by partition0[tag 0]
    const float off0   = fb[0] + trans[TSTART * NTAG + 0];
    float       offset = off0;
    float p0 = act ? __expf(fb[j] + trans[TSTART * NTAG + j] - off0) : 0.f;
    unsigned pju = b2u(__float2bfloat162_rn(p0));
    if (act) ((__nv_bfloat16*)spA)[j] = __low2bfloat16(u2b(pju));
    __syncthreads();

    const bool allOnes = (s_ones[0] + s_ones[1]) == SEQ;
    unsigned efw = s_ef[1 * NTAG + jf];

    if (allOnes) {
        // 8 steps per iteration (two rescale groups); t = 1..504
        for (int t = 1; t + 7 < SEQ; t += 8) {
            step_fast<false>(t,     j, jf, act, spA, spB, et2, efw, offset, s_ef);
            step_fast<false>(t + 1, j, jf, act, spB, spA, et2, efw, offset, s_ef);
            step_fast<false>(t + 2, j, jf, act, spA, spB, et2, efw, offset, s_ef);
            step_fast<true >(t + 3, j, jf, act, spB, spA, et2, efw, offset, s_ef);
            step_fast<false>(t + 4, j, jf, act, spA, spB, et2, efw, offset, s_ef);
            step_fast<false>(t + 5, j, jf, act, spB, spA, et2, efw, offset, s_ef);
            step_fast<false>(t + 6, j, jf, act, spA, spB, et2, efw, offset, s_ef);
            step_fast<true >(t + 7, j, jf, act, spB, spA, et2, efw, offset, s_ef);
        }
        // tail: t = 505..511 (7 steps; last inline without prefetch)
        step_fast<false>(SEQ - 7, j, jf, act, spA, spB, et2, efw, offset, s_ef);
        step_fast<false>(SEQ - 6, j, jf, act, spB, spA, et2, efw, offset, s_ef);
        step_fast<false>(SEQ - 5, j, jf, act, spA, spB, et2, efw, offset, s_ef);
        step_fast<true >(SEQ - 4, j, jf, act, spB, spA, et2, efw, offset, s_ef);
        step_fast<false>(SEQ - 3, j, jf, act, spA, spB, et2, efw, offset, s_ef);
        step_fast<false>(SEQ - 2, j, jf, act, spB, spA, et2, efw, offset, s_ef);
        {
            float p0f;
            __nv_bfloat162 s2 = gemv25(spA, et2, p0f);
            s2 = __hadd2(s2, u2b(swap16(b2u(s2))));
            __nv_bfloat162 q2 = __hmul2(s2, u2b(efw));
            if (act) ((__nv_bfloat16*)spB)[j] = __low2bfloat16(q2);
            __syncthreads();
        }
    } else {
        int m = s_mask[1];
        for (int t = 1; t + 3 < SEQ; t += 4) {
            step_gen<false>(t,     j, jf, act, spA, spB, et2, efw, pju, offset, m, s_ef, s_mask);
            step_gen<false>(t + 1, j, jf, act, spB, spA, et2, efw, pju, offset, m, s_ef, s_mask);
            step_gen<false>(t + 2, j, jf, act, spA, spB, et2, efw, pju, offset, m, s_ef, s_mask);
            step_gen<true >(t + 3, j, jf, act, spB, spA, et2, efw, pju, offset, m, s_ef, s_mask);
        }
        step_gen<false>(SEQ - 3, j, jf, act, spA, spB, et2, efw, pju, offset, m, s_ef, s_mask);
        step_gen<false>(SEQ - 2, j, jf, act, spB, spA, et2, efw, pju, offset, m, s_ef, s_mask);
        {
            float p0f;
            __nv_bfloat162 s2 = gemv25(spA, et2, p0f);
            s2 = __hadd2(s2, u2b(swap16(b2u(s2))));
            unsigned q2u = b2u(__hmul2(s2, u2b(efw)));
            q2u = m ? q2u : pju;
            if (act) ((__nv_bfloat16*)spB)[j] = __low2bfloat16(u2b(q2u));
            __syncthreads();
        }
    }
    // final partition lives in spB

    // terminal: forward = log( sum_i p[i]*exp(trans[i,STOP]) ) + offset
    if (j == TSTOP) {
        float p0f;
        __nv_bfloat162 s2 = gemv25(spB, et2, p0f);
        float2 sf = __bfloat1622float2(s2);
        s_fwd = __logf(sf.x + sf.y) + offset;
    }

    // ---- gold score ----
    float acc = 0.f;
    int   len = 0;
#pragma unroll
    for (int t = j; t < SEQ; t += NTHR) {
        int tag  = tb[t];
        int prev = (t == 0) ? TSTART : tb[t - 1];
        int mm   = s_mask[t];
        if (mm) acc += fb[t * NTAG + tag] + trans[prev * NTAG + tag];
        len += mm;
    }
    acc = warpSumF(acc);
    len = warpSumI(len);
    if (lane == 0) { s_acc[wid] = acc; s_len[wid] = len; }
    __syncthreads();

    if (j == 0) {
        int   L     = s_len[0] + s_len[1];
        int   endid = tb[L - 1];
        float gold  = s_acc[0] + s_acc[1] + trans[endid * NTAG + TSTOP];
        g_partial[b] = s_fwd - gold;
        __threadfence();
        unsigned tk = atomicAdd(&g_ticket, 1u);
        s_last = (tk == BATCH - 1);
    }
    __syncthreads();

    if (s_last) {
        float v = ((volatile float*)g_partial)[j];
        v = warpSumF(v);
        if (lane == 0) s_red2[wid] = v;
        __syncthreads();
        if (j == 0) {
            out[0] = s_red2[0] + s_red2[1];
            g_ticket = 0;
        }
    }
}

extern "C" void kernel_launch(void* const* d_in, const int* in_sizes, int n_in,
                              void* d_out, int out_size)
{
    const float* feats = (const float*)d_in[0];
    const int*   mask  = (const int*)d_in[1];
    const int*   tags  = (const int*)d_in[2];
    const float* trans = (const float*)d_in[3];
    float* out = (float*)d_out;

    cudaFuncSetAttribute(crf_kernel,
                         cudaFuncAttributeMaxDynamicSharedMemorySize, SMEM_BYTES);
    crf_kernel<<<BATCH, NTHR, SMEM_BYTES>>>(feats, mask, tags, trans, out);
}